// round 5
// baseline (speedup 1.0000x reference)
#include <cuda_runtime.h>
#include <cuda_bf16.h>
#include <cstdint>

#define NN 4096
#define BB 64
#define CC 64
#define EE 16
#define G  2            // batches per block (block N = 128)
#define KC 32           // K per chunk

// smem layout (bytes), pitch 80B per 32-bf16 row (64B data + 16 pad)
#define PKB   80
#define AHL   10240u          // A hi->lo offset (128*80)
#define BOFF  20480u          // B region start
#define BG    10240u          // per-batch B stride (hi+lo)
#define BHL   5120u           // B hi->lo offset (64*80)
#define STAGE 40960u          // one stage: A 20480 + B 20480
#define WOFF  81920u          // epi W region (2 k-halves x 10240)
#define SMEM_TOTAL 102400

// ---- device buffers (bf16 hi/lo splits) ----
__device__ __align__(16) __nv_bfloat16 g_Shi[(size_t)NN * NN];
__device__ __align__(16) __nv_bfloat16 g_Slo[(size_t)NN * NN];
__device__ __align__(16) __nv_bfloat16 g_Xhi[(size_t)BB * NN * CC];
__device__ __align__(16) __nv_bfloat16 g_Xlo[(size_t)BB * NN * CC];
__device__ __align__(16) __nv_bfloat16 g_B1Thi[(size_t)BB * CC * NN];
__device__ __align__(16) __nv_bfloat16 g_B1Tlo[(size_t)BB * CC * NN];
__device__ __align__(16) __nv_bfloat16 g_B2Thi[(size_t)BB * CC * NN];
__device__ __align__(16) __nv_bfloat16 g_B2Tlo[(size_t)BB * CC * NN];
__device__ __align__(16) __nv_bfloat16 g_W2Thi[CC * CC], g_W2Tlo[CC * CC];
__device__ __align__(16) __nv_bfloat16 g_W1Thi[CC * CC], g_W1Tlo[CC * CC];
__device__ __align__(16) __nv_bfloat16 g_WdThi[CC * CC], g_WdTlo[CC * CC];

__device__ __forceinline__ uint32_t smem_u32(const void* p) {
    uint32_t a;
    asm("{ .reg .u64 t; cvta.to.shared.u64 t, %1; cvt.u32.u64 %0, t; }" : "=r"(a) : "l"(p));
    return a;
}
__device__ __forceinline__ void ldsm4(uint32_t* r, uint32_t addr) {
    asm volatile("ldmatrix.sync.aligned.m8n8.x4.shared.b16 {%0,%1,%2,%3}, [%4];"
        : "=r"(r[0]), "=r"(r[1]), "=r"(r[2]), "=r"(r[3]) : "r"(addr));
}
__device__ __forceinline__ void mma16816(float* c, const uint32_t* a, const uint32_t* b) {
    asm volatile("mma.sync.aligned.m16n8k16.row.col.f32.bf16.bf16.f32 "
        "{%0,%1,%2,%3}, {%4,%5,%6,%7}, {%8,%9}, {%0,%1,%2,%3};"
        : "+f"(c[0]), "+f"(c[1]), "+f"(c[2]), "+f"(c[3])
        : "r"(a[0]), "r"(a[1]), "r"(a[2]), "r"(a[3]), "r"(b[0]), "r"(b[1]));
}
#define CPA(dst, src) \
    asm volatile("cp.async.cg.shared.global [%0], [%1], 16;" :: "r"(dst), "l"(src) : "memory")
#define CP_COMMIT() asm volatile("cp.async.commit_group;" ::: "memory")
#define CP_WAIT0()  asm volatile("cp.async.wait_group 0;" ::: "memory")
#define CP_WAIT1()  asm volatile("cp.async.wait_group 1;" ::: "memory")

// ---------------------------------------------------------------------------
__global__ __launch_bounds__(256) void supports_kernel(
    const float* __restrict__ adj, const float* __restrict__ emb)
{
    __shared__ float row[NN];
    __shared__ float red[8];
    const int n = blockIdx.x, tid = threadIdx.x;
    const int lane = tid & 31, wid = tid >> 5;

    float a[EE];
#pragma unroll
    for (int e = 0; e < EE; e++) a[e] = adj[n * EE + e];

    float mx = 0.0f;
#pragma unroll
    for (int j = 0; j < NN; j += 256) {
        int m = j + tid;
        float v = 0.0f;
#pragma unroll
        for (int e = 0; e < EE; e++) v = fmaf(a[e], emb[e * NN + m], v);
        v = fmaxf(v, 0.0f);
        row[m] = v;
        mx = fmaxf(mx, v);
    }
#pragma unroll
    for (int o = 16; o > 0; o >>= 1) mx = fmaxf(mx, __shfl_xor_sync(0xffffffffu, mx, o));
    if (lane == 0) red[wid] = mx;
    __syncthreads();
    mx = red[0];
#pragma unroll
    for (int w = 1; w < 8; w++) mx = fmaxf(mx, red[w]);
    __syncthreads();

    float s = 0.0f;
#pragma unroll
    for (int j = 0; j < NN; j += 256) {
        int m = j + tid;
        float e = __expf(row[m] - mx);
        row[m] = e;
        s += e;
    }
#pragma unroll
    for (int o = 16; o > 0; o >>= 1) s += __shfl_xor_sync(0xffffffffu, s, o);
    if (lane == 0) red[wid] = s;
    __syncthreads();
    s = 0.0f;
#pragma unroll
    for (int w = 0; w < 8; w++) s += red[w];
    const float inv = 1.0f / s;
#pragma unroll
    for (int j = 0; j < NN; j += 256) {
        int m = j + tid;
        float v = row[m] * inv;
        __nv_bfloat16 h = __float2bfloat16(v);
        size_t idx = (size_t)n * NN + m;
        g_Shi[idx] = h;
        g_Slo[idx] = __float2bfloat16(v - __bfloat162float(h));
    }
}

__global__ __launch_bounds__(256) void prep_x(const float* __restrict__ x)
{
    size_t i = (size_t)blockIdx.x * blockDim.x + threadIdx.x;  // float4 index
    float4 v = ((const float4*)x)[i];
    float f[4] = {v.x, v.y, v.z, v.w};
    __nv_bfloat16 h[4], l[4];
#pragma unroll
    for (int k = 0; k < 4; k++) {
        h[k] = __float2bfloat16(f[k]);
        l[k] = __float2bfloat16(f[k] - __bfloat162float(h[k]));
    }
    __nv_bfloat162* ph = (__nv_bfloat162*)g_Xhi;
    __nv_bfloat162* pl = (__nv_bfloat162*)g_Xlo;
    ph[2 * i]     = __nv_bfloat162{h[0], h[1]};
    ph[2 * i + 1] = __nv_bfloat162{h[2], h[3]};
    pl[2 * i]     = __nv_bfloat162{l[0], l[1]};
    pl[2 * i + 1] = __nv_bfloat162{l[2], l[3]};
}

__global__ void prep_w(const float* __restrict__ W)
{
#pragma unroll
    for (int q = 0; q < 16; q++) {
        int idx = threadIdx.x + q * 256;
        int i = idx >> 6, o = idx & 63;
        int t = o * CC + i;                     // transposed [o][i]
        float w0 = W[i * CC + o];
        float w1 = W[CC * CC + i * CC + o] * 0.5f;
        float w2 = W[2 * CC * CC + i * CC + o];
        float wd = w0 - w2;
        __nv_bfloat16 h;
        h = __float2bfloat16(w2); g_W2Thi[t] = h; g_W2Tlo[t] = __float2bfloat16(w2 - __bfloat162float(h));
        h = __float2bfloat16(w1); g_W1Thi[t] = h; g_W1Tlo[t] = __float2bfloat16(w1 - __bfloat162float(h));
        h = __float2bfloat16(wd); g_WdThi[t] = h; g_WdTlo[t] = __float2bfloat16(wd - __bfloat162float(h));
    }
}

// ---------------------------------------------------------------------------
// HMMA GEMM. Block 256 thr = 8 warps (4m x 2n); warp-n = batch. 2 CTAs/SM.
// mode 0: (epi only)  B1T = (X@W2)^T split
// mode 1: B2T = (2(S@B1) + X@W1)^T split      (W1 pre-scaled 0.5, out*2)
// mode 2: out = S@B2 + X@(W0-W2) + bias  (fp32)
// ---------------------------------------------------------------------------
__global__ __launch_bounds__(256, 2)
void cheb_gemm(const float* __restrict__ bias, float* __restrict__ out, int mode)
{
    extern __shared__ char smem[];
    const uint32_t sb = smem_u32(smem);
    const int tid = threadIdx.x, wid = tid >> 5, lane = tid & 31;
    const int wm = wid >> 1, wn = wid & 1;     // warp m-row, warp batch
    const int b0 = blockIdx.x * G;
    const int n0 = blockIdx.y * 128;
    const int m0 = wm * 32;

    const __nv_bfloat16* Bhi = (mode == 1) ? g_B1Thi : g_B2Thi;
    const __nv_bfloat16* Blo = (mode == 1) ? g_B1Tlo : g_B2Tlo;
    const __nv_bfloat16* WThi = (mode == 0) ? g_W2Thi : (mode == 1) ? g_W1Thi : g_WdThi;
    const __nv_bfloat16* WTlo = (mode == 0) ? g_W2Tlo : (mode == 1) ? g_W1Tlo : g_WdTlo;
    const int nMain = (mode == 0) ? 0 : (NN / KC);

    float acc[2][8][4];
#pragma unroll
    for (int a = 0; a < 2; a++)
#pragma unroll
        for (int b = 0; b < 8; b++)
#pragma unroll
            for (int c = 0; c < 4; c++) acc[a][b][c] = 0.0f;

    const uint32_t aRowOff = (uint32_t)(lane & 15) * PKB + ((lane >> 4) & 1) * 16;
    const uint32_t bRowOff = (uint32_t)((lane & 7) + ((lane >> 4) & 1) * 8) * PKB
                           + ((lane >> 3) & 1) * 16;

    auto load_main = [&](int cc) {
        const uint32_t st = sb + (uint32_t)(cc & 1) * STAGE;
        const int k0 = cc * KC;
#pragma unroll
        for (int q = 0; q < 4; q++) {           // A: 1024 16B ops
            int p = tid + 256 * q;
            int hl = p >> 9, r = (p >> 2) & 127, j = p & 3;
            const __nv_bfloat16* s = (hl ? g_Slo : g_Shi) + (size_t)(n0 + r) * NN + k0 + j * 8;
            CPA(st + (uint32_t)hl * AHL + (uint32_t)r * PKB + j * 16, s);
        }
#pragma unroll
        for (int q = 0; q < 4; q++) {           // B: 1024 16B ops
            int p = tid + 256 * q;
            int g = p >> 9, hl = (p >> 8) & 1, r = (p >> 2) & 63, j = p & 3;
            const __nv_bfloat16* s = (hl ? Blo : Bhi) +
                ((size_t)((b0 + g) * CC + r)) * NN + k0 + j * 8;
            CPA(st + BOFF + (uint32_t)g * BG + (uint32_t)hl * BHL + (uint32_t)r * PKB + j * 16, s);
        }
    };

    auto load_epi = [&]() {
#pragma unroll
        for (int q = 0; q < 16; q++) {          // X: 4096 ops (2 batches x 2 k-halves)
            int p = tid + 256 * q;
            int kh = p >> 11, g = (p >> 10) & 1, hl = (p >> 9) & 1;
            int r = (p >> 2) & 127, j = p & 3;
            const __nv_bfloat16* s = (hl ? g_Xlo : g_Xhi) +
                ((size_t)(b0 + g) * NN + n0 + r) * CC + kh * 32 + j * 8;
            CPA(sb + (uint32_t)kh * STAGE + (uint32_t)g * 20480u +
                (uint32_t)hl * AHL + (uint32_t)r * PKB + j * 16, s);
        }
#pragma unroll
        for (int q = 0; q < 4; q++) {           // W: 1024 ops (2 k-halves)
            int p = tid + 256 * q;
            int kh = p >> 9, hl = (p >> 8) & 1, r = (p >> 2) & 63, j = p & 3;
            const __nv_bfloat16* s = (hl ? WTlo : WThi) + r * CC + kh * 32 + j * 8;
            CPA(sb + WOFF + (uint32_t)kh * 10240u + (uint32_t)hl * BHL +
                (uint32_t)r * PKB + j * 16, s);
        }
    };

    auto do_chunk = [&](uint32_t aBase, uint32_t bBase) {
#pragma unroll
        for (int kk = 0; kk < 2; kk++) {
            uint32_t aH[8], aL[8];
#pragma unroll
            for (int mt = 0; mt < 2; mt++) {
                uint32_t ad = aBase + (uint32_t)(m0 + mt * 16) * PKB + kk * 32 + aRowOff;
                ldsm4(aH + 4 * mt, ad);
                ldsm4(aL + 4 * mt, ad + AHL);
            }
#pragma unroll
            for (int ntp = 0; ntp < 4; ntp++) {
                uint32_t bd = bBase + (uint32_t)(ntp * 16) * PKB + kk * 32 + bRowOff;
                uint32_t bH[4], bL[4];
                ldsm4(bH, bd);
                ldsm4(bL, bd + BHL);
#pragma unroll
                for (int mt = 0; mt < 2; mt++)
#pragma unroll
                    for (int h = 0; h < 2; h++) {
                        float* c = acc[mt][ntp * 2 + h];
                        mma16816(c, aH + 4 * mt, bH + 2 * h);
                        mma16816(c, aH + 4 * mt, bL + 2 * h);
                        mma16816(c, aL + 4 * mt, bH + 2 * h);
                    }
            }
        }
    };

    // ---- main K loop (double-buffered) ----
    if (nMain > 0) {
        load_main(0);
        CP_COMMIT();
        for (int c = 0; c < nMain; c++) {
            if (c + 1 < nMain) { load_main(c + 1); CP_COMMIT(); CP_WAIT1(); }
            else CP_WAIT0();
            __syncthreads();
            const uint32_t st = sb + (uint32_t)(c & 1) * STAGE;
            do_chunk(st, st + BOFF + (uint32_t)wn * BG);
            __syncthreads();
        }
    }

    // ---- epi chunks: X[b0+wn] @ W  (2 k-halves) ----
    load_epi();
    CP_COMMIT(); CP_WAIT0();
    __syncthreads();
#pragma unroll
    for (int kh = 0; kh < 2; kh++)
        do_chunk(sb + (uint32_t)kh * STAGE + (uint32_t)wn * 20480u,
                 sb + WOFF + (uint32_t)kh * 10240u);

    // ---- epilogue ----
    const int g = wn;
    const int rA = lane >> 2;
    const int c0 = (lane & 3) * 2;
    if (mode == 2) {
#pragma unroll
        for (int mt = 0; mt < 2; mt++) {
            int m = n0 + m0 + mt * 16 + rA;
#pragma unroll
            for (int nt = 0; nt < 8; nt++) {
                int col = nt * 8 + c0;
                float b0v = __ldg(bias + col), b1v = __ldg(bias + col + 1);
                size_t base = ((size_t)(b0 + g) * NN + m) * CC + col;
                *(float2*)(out + base) = make_float2(acc[mt][nt][0] + b0v, acc[mt][nt][1] + b1v);
                *(float2*)(out + base + 8 * CC) = make_float2(acc[mt][nt][2] + b0v, acc[mt][nt][3] + b1v);
            }
        }
    } else {
        __nv_bfloat16* dh = (mode == 0) ? g_B1Thi : g_B2Thi;
        __nv_bfloat16* dl = (mode == 0) ? g_B1Tlo : g_B2Tlo;
        const float sc = (mode == 1) ? 2.0f : 1.0f;
#pragma unroll
        for (int mt = 0; mt < 2; mt++) {
            int m = n0 + m0 + mt * 16 + rA;
#pragma unroll
            for (int nt = 0; nt < 8; nt++) {
                int col = nt * 8 + c0;
#pragma unroll
                for (int q = 0; q < 4; q++) {
                    float v = acc[mt][nt][q] * sc;
                    size_t o = ((size_t)((b0 + g) * CC + col + (q & 1))) * NN + m + (q >> 1) * 8;
                    __nv_bfloat16 h = __float2bfloat16(v);
                    dh[o] = h;
                    dl[o] = __float2bfloat16(v - __bfloat162float(h));
                }
            }
        }
    }
}

// ---------------------------------------------------------------------------
extern "C" void kernel_launch(void* const* d_in, const int* in_sizes, int n_in,
                              void* d_out, int out_size)
{
    const float* x    = (const float*)d_in[0];  // [64, 4096, 64]
    const float* adj  = (const float*)d_in[1];  // [4096, 16]
    const float* emb  = (const float*)d_in[2];  // [16, 4096]
    const float* W    = (const float*)d_in[3];  // [3, 64, 64]
    const float* bias = (const float*)d_in[4];  // [64]
    float* out = (float*)d_out;                 // [64, 4096, 64]
    (void)in_sizes; (void)n_in; (void)out_size;

    cudaFuncSetAttribute(cheb_gemm, cudaFuncAttributeMaxDynamicSharedMemorySize, SMEM_TOTAL);

    supports_kernel<<<NN, 256>>>(adj, emb);
    prep_x<<<(BB * NN * CC / 4) / 256, 256>>>(x);
    prep_w<<<1, 256>>>(W);

    dim3 grid(BB / G, NN / 128);
    cheb_gemm<<<grid, 256, SMEM_TOTAL>>>(bias, out, 0);  // B1 = X@W2
    cheb_gemm<<<grid, 256, SMEM_TOTAL>>>(bias, out, 1);  // B2 = 2(S@B1) + X@W1
    cheb_gemm<<<grid, 256, SMEM_TOTAL>>>(bias, out, 2);  // out = S@B2 + X@(W0-W2) + bias
}

// round 6
// speedup vs baseline: 2.6728x; 2.6728x over previous
#include <cuda_runtime.h>
#include <cuda_fp16.h>
#include <cstdint>

#define NN 4096
#define BB 64
#define CC 64
#define EE 16
#define G  2            // batches per block (block N = 128)
#define KC 64           // K per chunk

// smem: pitch 144B per 64-fp16 row (128B data + 16 pad)
#define PKB   144
#define ASZ   18432u          // A region 128*144
#define BGS   9216u           // per-batch B region 64*144
#define STAGE 36864u          // A + 2*B
#define NSTG  3
#define SMEM_TOTAL (3 * 36864)

// ---- device buffers (fp16) ----
__device__ __align__(16) __half g_Sh[(size_t)NN * NN];
__device__ __align__(16) __half g_Xh[(size_t)BB * NN * CC];
__device__ __align__(16) __half g_B1T[(size_t)BB * CC * NN];
__device__ __align__(16) __half g_B2T[(size_t)BB * CC * NN];
__device__ __align__(16) __half g_W2T[CC * CC], g_W1T[CC * CC], g_WdT[CC * CC];

__device__ __forceinline__ uint32_t smem_u32(const void* p) {
    uint32_t a;
    asm("{ .reg .u64 t; cvta.to.shared.u64 t, %1; cvt.u32.u64 %0, t; }" : "=r"(a) : "l"(p));
    return a;
}
__device__ __forceinline__ void ldsm4(uint32_t* r, uint32_t addr) {
    asm volatile("ldmatrix.sync.aligned.m8n8.x4.shared.b16 {%0,%1,%2,%3}, [%4];"
        : "=r"(r[0]), "=r"(r[1]), "=r"(r[2]), "=r"(r[3]) : "r"(addr));
}
__device__ __forceinline__ void mma16816(float* c, const uint32_t* a, const uint32_t* b) {
    asm volatile("mma.sync.aligned.m16n8k16.row.col.f32.f16.f16.f32 "
        "{%0,%1,%2,%3}, {%4,%5,%6,%7}, {%8,%9}, {%0,%1,%2,%3};"
        : "+f"(c[0]), "+f"(c[1]), "+f"(c[2]), "+f"(c[3])
        : "r"(a[0]), "r"(a[1]), "r"(a[2]), "r"(a[3]), "r"(b[0]), "r"(b[1]));
}
#define CPA(dst, src) \
    asm volatile("cp.async.cg.shared.global [%0], [%1], 16;" :: "r"(dst), "l"(src) : "memory")
#define CP_COMMIT() asm volatile("cp.async.commit_group;" ::: "memory")
#define CP_WAIT0()  asm volatile("cp.async.wait_group 0;" ::: "memory")
#define CP_WAIT1()  asm volatile("cp.async.wait_group 1;" ::: "memory")

// ---------------------------------------------------------------------------
__global__ __launch_bounds__(256) void supports_kernel(
    const float* __restrict__ adj, const float* __restrict__ emb)
{
    __shared__ float row[NN];
    __shared__ float red[8];
    const int n = blockIdx.x, tid = threadIdx.x;
    const int lane = tid & 31, wid = tid >> 5;

    float a[EE];
#pragma unroll
    for (int e = 0; e < EE; e++) a[e] = adj[n * EE + e];

    float mx = 0.0f;
#pragma unroll
    for (int j = 0; j < NN; j += 256) {
        int m = j + tid;
        float v = 0.0f;
#pragma unroll
        for (int e = 0; e < EE; e++) v = fmaf(a[e], emb[e * NN + m], v);
        v = fmaxf(v, 0.0f);
        row[m] = v;
        mx = fmaxf(mx, v);
    }
#pragma unroll
    for (int o = 16; o > 0; o >>= 1) mx = fmaxf(mx, __shfl_xor_sync(0xffffffffu, mx, o));
    if (lane == 0) red[wid] = mx;
    __syncthreads();
    mx = red[0];
#pragma unroll
    for (int w = 1; w < 8; w++) mx = fmaxf(mx, red[w]);
    __syncthreads();

    float s = 0.0f;
#pragma unroll
    for (int j = 0; j < NN; j += 256) {
        int m = j + tid;
        float e = __expf(row[m] - mx);
        row[m] = e;
        s += e;
    }
#pragma unroll
    for (int o = 16; o > 0; o >>= 1) s += __shfl_xor_sync(0xffffffffu, s, o);
    if (lane == 0) red[wid] = s;
    __syncthreads();
    s = 0.0f;
#pragma unroll
    for (int w = 0; w < 8; w++) s += red[w];
    const float inv = 1.0f / s;
#pragma unroll
    for (int j = 0; j < NN; j += 256) {
        int m = j + tid;
        g_Sh[(size_t)n * NN + m] = __float2half_rn(row[m] * inv);
    }
}

__global__ __launch_bounds__(256) void prep_x(const float* __restrict__ x)
{
    size_t i = (size_t)blockIdx.x * blockDim.x + threadIdx.x;  // float4 index
    float4 v = ((const float4*)x)[i];
    __half2* ph = (__half2*)g_Xh;
    ph[2 * i]     = __half2{__float2half_rn(v.x), __float2half_rn(v.y)};
    ph[2 * i + 1] = __half2{__float2half_rn(v.z), __float2half_rn(v.w)};
}

__global__ void prep_w(const float* __restrict__ W)
{
#pragma unroll
    for (int q = 0; q < 16; q++) {
        int idx = threadIdx.x + q * 256;
        int i = idx >> 6, o = idx & 63;
        int t = o * CC + i;                     // transposed [o][i]
        float w0 = W[i * CC + o];
        float w1 = W[CC * CC + i * CC + o] * 0.5f;
        float w2 = W[2 * CC * CC + i * CC + o];
        g_W2T[t] = __float2half_rn(w2);
        g_W1T[t] = __float2half_rn(w1);
        g_WdT[t] = __float2half_rn(w0 - w2);
    }
}

// ---------------------------------------------------------------------------
// fp16 HMMA GEMM. 256 thr = 8 warps (4m x 2n); warp-n = batch. 2 CTAs/SM.
// 3-stage cp.async pipeline, one barrier per KC=64 chunk.
// mode 0: (epi only)  B1T = (X@W2)^T
// mode 1: B2T = (2(S@B1) + X@W1)^T            (W1 pre-scaled 0.5, out*2)
// mode 2: out = S@B2 + X@(W0-W2) + bias  (fp32)
// ---------------------------------------------------------------------------
__global__ __launch_bounds__(256, 2)
void cheb_gemm(const float* __restrict__ bias, float* __restrict__ out, int mode)
{
    extern __shared__ char smem[];
    const uint32_t sb = smem_u32(smem);
    const int tid = threadIdx.x, wid = tid >> 5, lane = tid & 31;
    const int wm = wid >> 1, wn = wid & 1;
    const int b0 = blockIdx.x * G;
    const int n0 = blockIdx.y * 128;
    const int m0 = wm * 32;

    const __half* Bop = (mode == 1) ? g_B1T : g_B2T;
    const __half* WT  = (mode == 0) ? g_W2T : (mode == 1) ? g_W1T : g_WdT;
    const int nMain = (mode == 0) ? 0 : (NN / KC);

    float acc[2][8][4];
#pragma unroll
    for (int a = 0; a < 2; a++)
#pragma unroll
        for (int b = 0; b < 8; b++)
#pragma unroll
            for (int c = 0; c < 4; c++) acc[a][b][c] = 0.0f;

    const uint32_t aRowOff = (uint32_t)(lane & 15) * PKB + ((lane >> 4) & 1) * 16;
    const uint32_t bRowOff = (uint32_t)((lane & 7) + ((lane >> 4) & 1) * 8) * PKB
                           + ((lane >> 3) & 1) * 16;

    auto load_main = [&](int cc) {
        const uint32_t st = sb + (uint32_t)(cc % NSTG) * STAGE;
        const int k0 = cc * KC;
#pragma unroll
        for (int q = 0; q < 4; q++) {           // A: 1024 16B ops
            int p = tid + 256 * q;
            int r = p >> 3, j = p & 7;
            const __half* s = g_Sh + (size_t)(n0 + r) * NN + k0 + j * 8;
            CPA(st + (uint32_t)r * PKB + j * 16, s);
        }
#pragma unroll
        for (int q = 0; q < 4; q++) {           // B: 1024 16B ops
            int p = tid + 256 * q;
            int g = p >> 9, r = (p >> 3) & 63, j = p & 7;
            const __half* s = Bop + ((size_t)((b0 + g) * CC + r)) * NN + k0 + j * 8;
            CPA(st + ASZ + (uint32_t)g * BGS + (uint32_t)r * PKB + j * 16, s);
        }
    };

    auto load_epi = [&]() {
#pragma unroll
        for (int q = 0; q < 8; q++) {           // X: 2048 ops (2 batches)
            int p = tid + 256 * q;
            int g = p >> 10, r = (p >> 3) & 127, j = p & 7;
            const __half* s = g_Xh + ((size_t)(b0 + g) * NN + n0 + r) * CC + j * 8;
            CPA(sb + (uint32_t)g * STAGE + (uint32_t)r * PKB + j * 16, s);
        }
#pragma unroll
        for (int q = 0; q < 2; q++) {           // W: 512 ops
            int p = tid + 256 * q;
            int r = p >> 3, j = p & 7;
            const __half* s = WT + r * CC + j * 8;
            CPA(sb + 2u * STAGE + (uint32_t)r * PKB + j * 16, s);
        }
    };

    auto do_chunk = [&](uint32_t aBase, uint32_t bBase) {
#pragma unroll
        for (int kk = 0; kk < 4; kk++) {
            uint32_t a[2][4];
#pragma unroll
            for (int mt = 0; mt < 2; mt++)
                ldsm4(a[mt], aBase + (uint32_t)(m0 + mt * 16) * PKB + kk * 32 + aRowOff);
#pragma unroll
            for (int ntp = 0; ntp < 4; ntp++) {
                uint32_t b[4];
                ldsm4(b, bBase + (uint32_t)(ntp * 16) * PKB + kk * 32 + bRowOff);
#pragma unroll
                for (int mt = 0; mt < 2; mt++)
#pragma unroll
                    for (int h = 0; h < 2; h++)
                        mma16816(acc[mt][ntp * 2 + h], a[mt], b + 2 * h);
            }
        }
    };

    // ---- main K loop: 3-stage pipeline, one barrier per chunk ----
    if (nMain > 0) {
        load_main(0); CP_COMMIT();
        load_main(1); CP_COMMIT();
        for (int c = 0; c < nMain; c++) {
            if (c + 2 <= nMain) CP_WAIT1(); else CP_WAIT0();
            __syncthreads();
            if (c + 2 < nMain) { load_main(c + 2); CP_COMMIT(); }
            const uint32_t st = sb + (uint32_t)(c % NSTG) * STAGE;
            do_chunk(st, st + ASZ + (uint32_t)wn * BGS);
        }
        __syncthreads();   // all warps done reading stages before epi overwrite
    }

    // ---- epi chunk: X[b0+wn] @ W (K=64 = one chunk) ----
    load_epi();
    CP_COMMIT(); CP_WAIT0();
    __syncthreads();
    do_chunk(sb + (uint32_t)wn * STAGE, sb + 2u * STAGE);

    // ---- epilogue ----
    const int g = wn;
    const int rA = lane >> 2;
    const int c0 = (lane & 3) * 2;
    if (mode == 2) {
#pragma unroll
        for (int mt = 0; mt < 2; mt++) {
            int m = n0 + m0 + mt * 16 + rA;
#pragma unroll
            for (int nt = 0; nt < 8; nt++) {
                int col = nt * 8 + c0;
                float b0v = __ldg(bias + col), b1v = __ldg(bias + col + 1);
                size_t base = ((size_t)(b0 + g) * NN + m) * CC + col;
                *(float2*)(out + base) = make_float2(acc[mt][nt][0] + b0v, acc[mt][nt][1] + b1v);
                *(float2*)(out + base + 8 * CC) = make_float2(acc[mt][nt][2] + b0v, acc[mt][nt][3] + b1v);
            }
        }
    } else {
        __half* dh = (mode == 0) ? g_B1T : g_B2T;
        const float sc = (mode == 1) ? 2.0f : 1.0f;
#pragma unroll
        for (int mt = 0; mt < 2; mt++) {
            int m = n0 + m0 + mt * 16 + rA;
#pragma unroll
            for (int nt = 0; nt < 8; nt++) {
                int col = nt * 8 + c0;
#pragma unroll
                for (int q = 0; q < 4; q++) {
                    float v = acc[mt][nt][q] * sc;
                    size_t o = ((size_t)((b0 + g) * CC + col + (q & 1))) * NN + m + (q >> 1) * 8;
                    dh[o] = __float2half_rn(v);
                }
            }
        }
    }
}

// ---------------------------------------------------------------------------
extern "C" void kernel_launch(void* const* d_in, const int* in_sizes, int n_in,
                              void* d_out, int out_size)
{
    const float* x    = (const float*)d_in[0];  // [64, 4096, 64]
    const float* adj  = (const float*)d_in[1];  // [4096, 16]
    const float* emb  = (const float*)d_in[2];  // [16, 4096]
    const float* W    = (const float*)d_in[3];  // [3, 64, 64]
    const float* bias = (const float*)d_in[4];  // [64]
    float* out = (float*)d_out;                 // [64, 4096, 64]
    (void)in_sizes; (void)n_in; (void)out_size;

    cudaFuncSetAttribute(cheb_gemm, cudaFuncAttributeMaxDynamicSharedMemorySize, SMEM_TOTAL);

    supports_kernel<<<NN, 256>>>(adj, emb);
    prep_x<<<(BB * NN * CC / 4) / 256, 256>>>(x);
    prep_w<<<1, 256>>>(W);

    dim3 grid(BB / G, NN / 128);
    cheb_gemm<<<grid, 256, SMEM_TOTAL>>>(bias, out, 0);  // B1 = X@W2
    cheb_gemm<<<grid, 256, SMEM_TOTAL>>>(bias, out, 1);  // B2 = 2(S@B1) + X@W1
    cheb_gemm<<<grid, 256, SMEM_TOTAL>>>(bias, out, 2);  // out = S@B2 + X@(W0-W2) + bias
}